// round 11
// baseline (speedup 1.0000x reference)
#include <cuda_runtime.h>
#include <cuda_bf16.h>
#include <math.h>

// Problem constants
#define BB   32
#define HH   14
#define WW   14
#define CC   32
#define KK   64
#define KS   5
#define OH   10
#define OW   10
#define PP   100      // OH*OW
#define NPOS 196      // H*W
#define MM   800      // KS*KS*C
#define IMG  6272     // NPOS*CC floats per batch
#define SIGB 1229312  // NPOS*NPOS*CC floats per batch of Sigma_in
#define SIGR 6304     // NPOS*CC + CC (diag row stride in floats)
#define PSTR 36       // padded smem stride per position (floats)

// Scratch (device globals)
__device__ float4 g_w4[25 * 16 * KK];      // [ij][c2][k] = {w_ev, w_od, w2_ev, w2_od}
__device__ float  g_dv[BB * PP * KK];      // diag_vals
__device__ float  g_G [BB * PP * PP];      // Gram matrices
__device__ float  g_S [BB * NPOS * NPOS];  // position-Gram S = X X^T (4.9 MB)

// ---------------- f32x2 packed helpers ----------------
typedef unsigned long long ull;

__device__ __forceinline__ ull f2fma(ull a, ull b, ull c) {
    ull d;
    asm("fma.rn.f32x2 %0, %1, %2, %3;" : "=l"(d) : "l"(a), "l"(b), "l"(c));
    return d;
}
__device__ __forceinline__ float f2sum(ull v) {
    float lo, hi;
    asm("mov.b64 {%0, %1}, %2;" : "=f"(lo), "=f"(hi) : "l"(v));
    return lo + hi;
}

// ---------------- Kernel 0: weight pack (tiny, wide) ----------------
__global__ __launch_bounds__(256) void k_prep_w(const float* __restrict__ w_mu) {
    int idx = blockIdx.x * 256 + threadIdx.x;        // 25600 total
    if (idx >= 25600) return;
    int ij = idx >> 10;
    int r  = idx & 1023;
    int c2 = r >> 6;
    int k  = r & 63;
    float w0 = w_mu[(ij * 32 + 2 * c2) * KK + k];
    float w1 = w_mu[(ij * 32 + 2 * c2 + 1) * KK + k];
    g_w4[idx] = make_float4(w0, w1, w0 * w0, w1 * w1);
}

// ---------------- Kernel A: mu_out + diag_vals ----------------
// grid (5 pt, 4 kq, 32 b) = 640 blocks, 160 threads (5 warps).
// kk = tid&15 (one k of this quarter), pg = tid>>4 (0..9) owns p_local = pg*2 + {0,1}.
__global__ __launch_bounds__(160) void k_mu_diag(const float* __restrict__ mu_in,
                                                 const float* __restrict__ Sg,
                                                 const float* __restrict__ w_sigma,
                                                 float* __restrict__ out_mu) {
    __shared__ __align__(16) float4 s_w4[256];       // [c2(16)][kk(16)]
    __shared__ __align__(16) float  s_mu[84 * PSTR]; // 6 rows x 14 pos, padded
    __shared__ __align__(16) float  s_ds[84 * PSTR];
    __shared__ float s_S[84];
    __shared__ float s_tr[20];

    int tid = threadIdx.x;
    int pt  = blockIdx.x;            // output rows 2pt, 2pt+1
    int kq  = blockIdx.y;            // k quarter
    int b   = blockIdx.z;
    int kk  = tid & 15;
    int pg  = tid >> 4;              // 0..9

    // --- prefetch weight stage 0 (tap 0, this k-quarter) ---
    float4 pf0, pf1;
    {
        int f0 = tid;
        pf0 = __ldg(g_w4 + (f0 >> 4) * 64 + kq * 16 + (f0 & 15));
        if (tid < 96) {
            int f1 = tid + 160;
            pf1 = __ldg(g_w4 + (f1 >> 4) * 64 + kq * 16 + (f1 & 15));
        }
    }

    // --- fused load: mu tile (6 image rows) + Sigma-diag gather + channel sums ---
    {
        const float4* msrc = reinterpret_cast<const float4*>(mu_in + b * IMG + pt * 28 * 32);
        const float*  sb   = Sg + b * SIGB;
        for (int t = tid; t < 672; t += 160) {
            int pos_l = t >> 3;                      // 0..83
            int c4    = t & 7;
            float4 mv = msrc[t];
            *reinterpret_cast<float4*>(s_mu + pos_l * PSTR + c4 * 4) = mv;
            int pos = pt * 28 + pos_l;
            float4 sg = *reinterpret_cast<const float4*>(sb + pos * SIGR + c4 * 4);
            *reinterpret_cast<float4*>(s_ds + pos_l * PSTR + c4 * 4) = sg;
            float part = sg.x + sg.y + sg.z + sg.w;
            part += __shfl_down_sync(0xffffffffu, part, 4, 8);
            part += __shfl_down_sync(0xffffffffu, part, 2, 8);
            part += __shfl_down_sync(0xffffffffu, part, 1, 8);
            if (c4 == 0) s_S[pos_l] = part;
        }
    }
    __syncthreads();

    // --- trace per patch (20 p's) ---
    if (tid < 20) {
        int pr = tid / 10, pc = tid % 10;
        float s = 0.f;
        #pragma unroll
        for (int i = 0; i < KS; i++)
            #pragma unroll
            for (int j = 0; j < KS; j++)
                s += s_S[(pr + i) * 14 + pc + j];
        s_tr[tid] = s;
    }

    // p bases for this thread's 2 patches
    int pbase[2];
    #pragma unroll
    for (int jp = 0; jp < 2; jp++) {
        int pl = pg * 2 + jp;                        // 0..19
        int pr = pl / 10, pc = pl % 10;
        pbase[jp] = (pr * 14 + pc) * PSTR;
    }

    ull accM[2], accV[2];
    accM[0] = accM[1] = accV[0] = accV[1] = 0ull;

    // --- main loop over 25 kernel taps ---
    #pragma unroll 1
    for (int ij = 0; ij < 25; ij++) {
        __syncthreads();                 // previous tap's reads of s_w4 complete
        s_w4[tid] = pf0;
        if (tid < 96) s_w4[tid + 160] = pf1;
        if (ij + 1 < 25) {
            const float4* ws = g_w4 + (ij + 1) * 1024 + kq * 16;
            int f0 = tid;
            pf0 = __ldg(ws + (f0 >> 4) * 64 + (f0 & 15));
            if (tid < 96) {
                int f1 = tid + 160;
                pf1 = __ldg(ws + (f1 >> 4) * 64 + (f1 & 15));
            }
        }
        __syncthreads();                 // stage ij visible

        int i = ij / 5, j = ij % 5;
        int sh = (i * 14 + j) * PSTR;

        #pragma unroll
        for (int c4 = 0; c4 < 8; c4++) {
            ulonglong2 wA = *reinterpret_cast<const ulonglong2*>(s_w4 + (2 * c4) * 16 + kk);
            ulonglong2 wB = *reinterpret_cast<const ulonglong2*>(s_w4 + (2 * c4 + 1) * 16 + kk);
            #pragma unroll
            for (int jp = 0; jp < 2; jp++) {
                int off = pbase[jp] + sh + c4 * 4;
                ulonglong2 a = *reinterpret_cast<const ulonglong2*>(s_mu + off);
                ulonglong2 d = *reinterpret_cast<const ulonglong2*>(s_ds + off);
                accM[jp] = f2fma(a.x, wA.x, accM[jp]);
                accM[jp] = f2fma(a.y, wB.x, accM[jp]);
                accV[jp] = f2fma(d.x, wA.y, accV[jp]);
                accV[jp] = f2fma(d.y, wB.y, accV[jp]);
            }
        }
    }

    int kg = kq * 16 + kk;
    float spk = log1pf(expf(w_sigma[kg]));
    #pragma unroll
    for (int jp = 0; jp < 2; jp++) {
        int pl = pg * 2 + jp;
        int p  = pt * 20 + pl;
        int base = (b * PP + p) * KK + kg;
        out_mu[base] = f2sum(accM[jp]);
        g_dv[base]   = f2sum(accV[jp]) + spk * s_tr[pl];
    }
}

// ---------------- Kernel B1: S = X X^T (wide) ----------------
__global__ __launch_bounds__(256) void k_gram_s(const float* __restrict__ mu_in) {
    __shared__ __align__(16) float2 s_yc[16 * 200];   // [c2][pos], padded

    int tid = threadIdx.x;
    int b   = blockIdx.y;
    int x0  = blockIdx.x * 28;
    const float* mb = mu_in + b * IMG;

    for (int t = tid; t < 16 * NPOS; t += 256) {
        int c2 = t & 15, pos = t >> 4;
        s_yc[c2 * 200 + pos] = *reinterpret_cast<const float2*>(mb + pos * 32 + c2 * 2);
    }
    __syncthreads();

    int lane = tid & 31, wrp = tid >> 5;
    float* Sb = g_S + b * (NPOS * NPOS);

    #pragma unroll 1
    for (int r = 0; r < 4; r++) {
        int xl = wrp + 8 * r;
        if (xl >= 28) break;
        int x = x0 + xl;

        ull xc[16];
        #pragma unroll
        for (int c2 = 0; c2 < 16; c2++)
            xc[c2] = *reinterpret_cast<const ull*>(s_yc + c2 * 200 + x);   // broadcast

        #pragma unroll 1
        for (int m = 0; m < 4; m++) {
            int pr = lane + 32 * m;
            if (pr >= 98) break;
            int y0 = 2 * pr;
            ull acc0 = 0ull, acc1 = 0ull;
            #pragma unroll
            for (int c2 = 0; c2 < 16; c2++) {
                ulonglong2 v = *reinterpret_cast<const ulonglong2*>(s_yc + c2 * 200 + y0);
                acc0 = f2fma(xc[c2], v.x, acc0);
                acc1 = f2fma(xc[c2], v.y, acc1);
            }
            float2 rr;
            rr.x = f2sum(acc0);
            rr.y = f2sum(acc1);
            *reinterpret_cast<float2*>(Sb + x * NPOS + y0) = rr;
        }
    }
}

// ---------------- Kernel B2: G[p,q] = 25-shift diagonal sum of S ----------------
__global__ __launch_bounds__(256) void k_gram_g() {
    int tid = threadIdx.x;
    int pt  = blockIdx.x;
    int b   = blockIdx.y;
    const float* Sb = g_S + b * (NPOS * NPOS);
    float* Gb = g_G + b * (PP * PP);

    #pragma unroll 1
    for (int idx = tid; idx < 25 * PP; idx += 256) {
        int p_l = idx / PP, q = idx - p_l * PP;
        int p  = pt * 25 + p_l;
        int pr = p / 10, pc = p - pr * 10;
        int qr = q / 10, qc = q - qr * 10;
        const float* s = Sb + (pr * 14 + pc) * NPOS + (qr * 14 + qc);
        float acc = 0.f;
        #pragma unroll
        for (int i = 0; i < KS; i++)
            #pragma unroll
            for (int j = 0; j < KS; j++)
                acc += __ldg(s + (i * 14 + j) * (NPOS + 1));
        Gb[p * PP + q] = acc;
    }
}

// ---------------- Kernel C1: expand Sigma_out off-diagonal rows (q != p) ----------------
__global__ __launch_bounds__(256) void k_expand_off(const float* __restrict__ w_sigma,
                                                    float* __restrict__ out) {
    __shared__ float  s_g[PP];
    __shared__ float4 s_sp[16];

    int tid = threadIdx.x;
    int p = blockIdx.x, b = blockIdx.y;
    int bp = b * PP + p;

    if (tid < PP) s_g[tid] = g_G[b * (PP * PP) + p * PP + tid];
    if (tid >= 128 && tid < 144) {
        int k4 = (tid - 128) * 4;
        float4 sp;
        sp.x = log1pf(expf(w_sigma[k4]));
        sp.y = log1pf(expf(w_sigma[k4 + 1]));
        sp.z = log1pf(expf(w_sigma[k4 + 2]));
        sp.w = log1pf(expf(w_sigma[k4 + 3]));
        s_sp[tid - 128] = sp;
    }
    __syncthreads();

    float* orow = out + BB * PP * KK + bp * (PP * KK);

    #pragma unroll
    for (int it = 0; it < 7; it++) {
        int v = tid + it * 256;
        if (v < PP * 16) {
            int q = v >> 4;
            if (q == p) continue;                    // diagonal row handled elsewhere
            int kc = v & 15, k4 = kc * 4;
            float g = s_g[q];
            float4 sp = s_sp[kc];
            float4 r;
            r.x = sp.x * g; r.y = sp.y * g; r.z = sp.z * g; r.w = sp.w * g;
            r.x = isfinite(r.x) ? r.x : 0.f;
            r.y = isfinite(r.y) ? r.y : 0.f;
            r.z = isfinite(r.z) ? r.z : 0.f;
            r.w = isfinite(r.w) ? r.w : 0.f;
            if (q == k4)     r.x = fabsf(r.x);
            if (q == k4 + 1) r.y = fabsf(r.y);
            if (q == k4 + 2) r.z = fabsf(r.z);
            if (q == k4 + 3) r.w = fabsf(r.w);
            *reinterpret_cast<float4*>(orow + 4 * v) = r;
        }
    }
}

// ---------------- Kernel C2: expand diagonal rows (q == p) ----------------
__global__ __launch_bounds__(256) void k_expand_diag(const float* __restrict__ w_sigma,
                                                     float* __restrict__ out) {
    int v = blockIdx.x * 256 + threadIdx.x;          // float4 index, 51200 total
    if (v >= BB * PP * 16) return;
    int bp = v >> 4, kc = v & 15, k4 = kc * 4;
    int b = bp / PP, p = bp - b * PP;

    float g = g_G[b * (PP * PP) + p * PP + p];
    float4 dv4 = *reinterpret_cast<const float4*>(g_dv + bp * KK + k4);
    float4 r;
    r.x = log1pf(expf(w_sigma[k4]))     * g + dv4.x;
    r.y = log1pf(expf(w_sigma[k4 + 1])) * g + dv4.y;
    r.z = log1pf(expf(w_sigma[k4 + 2])) * g + dv4.z;
    r.w = log1pf(expf(w_sigma[k4 + 3])) * g + dv4.w;
    r.x = isfinite(r.x) ? r.x : 0.f;
    r.y = isfinite(r.y) ? r.y : 0.f;
    r.z = isfinite(r.z) ? r.z : 0.f;
    r.w = isfinite(r.w) ? r.w : 0.f;
    if (p == k4)     r.x = fabsf(r.x);
    if (p == k4 + 1) r.y = fabsf(r.y);
    if (p == k4 + 2) r.z = fabsf(r.z);
    if (p == k4 + 3) r.w = fabsf(r.w);
    float* orow = out + BB * PP * KK + bp * (PP * KK) + p * KK;
    *reinterpret_cast<float4*>(orow + k4) = r;
}

// ---------------- launch ----------------
extern "C" void kernel_launch(void* const* d_in, const int* in_sizes, int n_in,
                              void* d_out, int out_size) {
    const float* mu_in    = (const float*)d_in[0];
    const float* Sigma_in = (const float*)d_in[1];
    const float* w_mu     = (const float*)d_in[2];
    const float* w_sigma  = (const float*)d_in[3];
    float* out = (float*)d_out;

    static cudaStream_t s2 = nullptr;
    static cudaEvent_t  eFork = nullptr, eJoin = nullptr;
    if (s2 == nullptr) {
        cudaStreamCreateWithFlags(&s2, cudaStreamNonBlocking);
        cudaEventCreateWithFlags(&eFork, cudaEventDisableTiming);
        cudaEventCreateWithFlags(&eJoin, cudaEventDisableTiming);
    }

    // side stream: Gram chain + off-diagonal Sigma expansion (no mu dependency)
    cudaEventRecord(eFork, 0);
    cudaStreamWaitEvent(s2, eFork, 0);
    k_gram_s<<<dim3(7, BB), 256, 0, s2>>>(mu_in);
    k_gram_g<<<dim3(4, BB), 256, 0, s2>>>();
    k_expand_off<<<dim3(PP, BB), 256, 0, s2>>>(w_sigma, out);
    cudaEventRecord(eJoin, s2);

    // main stream: mu path
    k_prep_w<<<100, 256>>>(w_mu);
    k_mu_diag<<<dim3(5, 4, BB), 160>>>(mu_in, Sigma_in, w_sigma, out);

    cudaStreamWaitEvent(0, eJoin, 0);
    k_expand_diag<<<200, 256>>>(w_sigma, out);
}

// round 13
// speedup vs baseline: 1.0685x; 1.0685x over previous
#include <cuda_runtime.h>
#include <cuda_bf16.h>
#include <math.h>

// Problem constants
#define BB   32
#define HH   14
#define WW   14
#define CC   32
#define KK   64
#define KS   5
#define OH   10
#define OW   10
#define PP   100      // OH*OW
#define NPOS 196      // H*W
#define MM   800      // KS*KS*C
#define IMG  6272     // NPOS*CC floats per batch
#define SIGB 1229312  // NPOS*NPOS*CC floats per batch of Sigma_in
#define SIGR 6304     // NPOS*CC + CC (diag row stride in floats)
#define PSTR 36       // padded smem stride per position (floats)

// Scratch (device globals)
__device__ float4 g_w4[25 * 16 * KK];      // [ij][c2][k] = {w_ev, w_od, w2_ev, w2_od}
__device__ float  g_dv[BB * PP * KK];      // diag_vals
__device__ float  g_G [BB * PP * PP];      // Gram matrices
__device__ float  g_S [BB * NPOS * NPOS];  // position-Gram S = X X^T (4.9 MB)

// ---------------- f32x2 packed helpers ----------------
typedef unsigned long long ull;

__device__ __forceinline__ ull f2fma(ull a, ull b, ull c) {
    ull d;
    asm("fma.rn.f32x2 %0, %1, %2, %3;" : "=l"(d) : "l"(a), "l"(b), "l"(c));
    return d;
}
__device__ __forceinline__ float f2sum(ull v) {
    float lo, hi;
    asm("mov.b64 {%0, %1}, %2;" : "=f"(lo), "=f"(hi) : "l"(v));
    return lo + hi;
}

// ---------------- Kernel 0: weight pack (tiny, wide) ----------------
__global__ __launch_bounds__(256) void k_prep_w(const float* __restrict__ w_mu) {
    int idx = blockIdx.x * 256 + threadIdx.x;        // 25600 total
    if (idx >= 25600) return;
    int ij = idx >> 10;
    int r  = idx & 1023;
    int c2 = r >> 6;
    int k  = r & 63;
    float w0 = w_mu[(ij * 32 + 2 * c2) * KK + k];
    float w1 = w_mu[(ij * 32 + 2 * c2 + 1) * KK + k];
    g_w4[idx] = make_float4(w0, w1, w0 * w0, w1 * w1);
}

// ---------------- Kernel A: mu_out + diag_vals ----------------
// grid (5 pt, 4 kq, 32 b) = 640 blocks, 160 threads (5 warps), 5 blocks/SM forced.
// kk = tid&15, pg = tid>>4 (0..9) owns p_local = pg*2 + {0,1}.
// Weights: double-buffered 4KB stage per tap, ONE sync per tap.
__global__ __launch_bounds__(160, 5) void k_mu_diag(const float* __restrict__ mu_in,
                                                    const float* __restrict__ Sg,
                                                    const float* __restrict__ w_sigma,
                                                    float* __restrict__ out_mu) {
    __shared__ __align__(16) float4 s_w4[2][256];    // double buffer [c2(16)][kk(16)]
    __shared__ __align__(16) float  s_mu[84 * PSTR]; // 6 rows x 14 pos, padded
    __shared__ __align__(16) float  s_ds[84 * PSTR];
    __shared__ float s_S[84];
    __shared__ float s_tr[20];

    int tid = threadIdx.x;
    int pt  = blockIdx.x;            // output rows 2pt, 2pt+1
    int kq  = blockIdx.y;            // k quarter
    int b   = blockIdx.z;
    int kk  = tid & 15;
    int pg  = tid >> 4;              // 0..9

    // --- prefetch weight stage 0 (tap 0, this k-quarter) ---
    float4 pf0, pf1;
    {
        int f0 = tid;
        pf0 = __ldg(g_w4 + (f0 >> 4) * 64 + kq * 16 + (f0 & 15));
        if (tid < 96) {
            int f1 = tid + 160;
            pf1 = __ldg(g_w4 + (f1 >> 4) * 64 + kq * 16 + (f1 & 15));
        }
    }

    // --- fused load: mu tile (6 image rows) + Sigma-diag gather + channel sums ---
    {
        const float4* msrc = reinterpret_cast<const float4*>(mu_in + b * IMG + pt * 28 * 32);
        const float*  sb   = Sg + b * SIGB;
        for (int t = tid; t < 672; t += 160) {
            int pos_l = t >> 3;                      // 0..83
            int c4    = t & 7;
            float4 mv = msrc[t];
            *reinterpret_cast<float4*>(s_mu + pos_l * PSTR + c4 * 4) = mv;
            int pos = pt * 28 + pos_l;
            float4 sg = *reinterpret_cast<const float4*>(sb + pos * SIGR + c4 * 4);
            *reinterpret_cast<float4*>(s_ds + pos_l * PSTR + c4 * 4) = sg;
            float part = sg.x + sg.y + sg.z + sg.w;
            part += __shfl_down_sync(0xffffffffu, part, 4, 8);
            part += __shfl_down_sync(0xffffffffu, part, 2, 8);
            part += __shfl_down_sync(0xffffffffu, part, 1, 8);
            if (c4 == 0) s_S[pos_l] = part;
        }
    }

    // --- store stage 0 into buffer 0 (before the single pre-loop sync) ---
    s_w4[0][tid] = pf0;
    if (tid < 96) s_w4[0][tid + 160] = pf1;
    __syncthreads();                 // image tile + stage 0 visible

    // --- trace per patch (20 p's); consumed only after mainloop syncs ---
    if (tid < 20) {
        int pr = tid / 10, pc = tid % 10;
        float s = 0.f;
        #pragma unroll
        for (int i = 0; i < KS; i++)
            #pragma unroll
            for (int j = 0; j < KS; j++)
                s += s_S[(pr + i) * 14 + pc + j];
        s_tr[tid] = s;
    }

    // prefetch stage 1
    {
        const float4* ws = g_w4 + 1024 + kq * 16;
        int f0 = tid;
        pf0 = __ldg(ws + (f0 >> 4) * 64 + (f0 & 15));
        if (tid < 96) {
            int f1 = tid + 160;
            pf1 = __ldg(ws + (f1 >> 4) * 64 + (f1 & 15));
        }
    }

    // p bases for this thread's 2 patches
    int pbase[2];
    #pragma unroll
    for (int jp = 0; jp < 2; jp++) {
        int pl = pg * 2 + jp;                        // 0..19
        int pr = pl / 10, pc = pl % 10;
        pbase[jp] = (pr * 14 + pc) * PSTR;
    }

    ull accM[2], accV[2];
    accM[0] = accM[1] = accV[0] = accV[1] = 0ull;

    // --- main loop over 25 kernel taps, ONE sync per tap ---
    #pragma unroll 1
    for (int ij = 0; ij < 25; ij++) {
        int i = ij / 5, j = ij % 5;
        int sh = (i * 14 + j) * PSTR;
        const float4* wbuf = s_w4[ij & 1];

        // store next stage into the other buffer (no reader conflict)
        if (ij + 1 < 25) {
            float4* nbuf = s_w4[(ij + 1) & 1];
            nbuf[tid] = pf0;
            if (tid < 96) nbuf[tid + 160] = pf1;
            if (ij + 2 < 25) {
                const float4* ws = g_w4 + (ij + 2) * 1024 + kq * 16;
                int f0 = tid;
                pf0 = __ldg(ws + (f0 >> 4) * 64 + (f0 & 15));
                if (tid < 96) {
                    int f1 = tid + 160;
                    pf1 = __ldg(ws + (f1 >> 4) * 64 + (f1 & 15));
                }
            }
        }

        #pragma unroll
        for (int c4 = 0; c4 < 8; c4++) {
            ulonglong2 wA = *reinterpret_cast<const ulonglong2*>(wbuf + (2 * c4) * 16 + kk);
            ulonglong2 wB = *reinterpret_cast<const ulonglong2*>(wbuf + (2 * c4 + 1) * 16 + kk);
            #pragma unroll
            for (int jp = 0; jp < 2; jp++) {
                int off = pbase[jp] + sh + c4 * 4;
                ulonglong2 a = *reinterpret_cast<const ulonglong2*>(s_mu + off);
                ulonglong2 d = *reinterpret_cast<const ulonglong2*>(s_ds + off);
                accM[jp] = f2fma(a.x, wA.x, accM[jp]);
                accM[jp] = f2fma(a.y, wB.x, accM[jp]);
                accV[jp] = f2fma(d.x, wA.y, accV[jp]);
                accV[jp] = f2fma(d.y, wB.y, accV[jp]);
            }
        }
        __syncthreads();             // next stage visible; buffer reads complete
    }

    int kg = kq * 16 + kk;
    float spk = log1pf(expf(w_sigma[kg]));
    #pragma unroll
    for (int jp = 0; jp < 2; jp++) {
        int pl = pg * 2 + jp;
        int p  = pt * 20 + pl;
        int base = (b * PP + p) * KK + kg;
        out_mu[base] = f2sum(accM[jp]);
        g_dv[base]   = f2sum(accV[jp]) + spk * s_tr[pl];
    }
}

// ---------------- Kernel B1: S = X X^T (wide) ----------------
__global__ __launch_bounds__(256) void k_gram_s(const float* __restrict__ mu_in) {
    __shared__ __align__(16) float2 s_yc[16 * 200];   // [c2][pos], padded

    int tid = threadIdx.x;
    int b   = blockIdx.y;
    int x0  = blockIdx.x * 28;
    const float* mb = mu_in + b * IMG;

    for (int t = tid; t < 16 * NPOS; t += 256) {
        int c2 = t & 15, pos = t >> 4;
        s_yc[c2 * 200 + pos] = *reinterpret_cast<const float2*>(mb + pos * 32 + c2 * 2);
    }
    __syncthreads();

    int lane = tid & 31, wrp = tid >> 5;
    float* Sb = g_S + b * (NPOS * NPOS);

    #pragma unroll 1
    for (int r = 0; r < 4; r++) {
        int xl = wrp + 8 * r;
        if (xl >= 28) break;
        int x = x0 + xl;

        ull xc[16];
        #pragma unroll
        for (int c2 = 0; c2 < 16; c2++)
            xc[c2] = *reinterpret_cast<const ull*>(s_yc + c2 * 200 + x);   // broadcast

        #pragma unroll 1
        for (int m = 0; m < 4; m++) {
            int pr = lane + 32 * m;
            if (pr >= 98) break;
            int y0 = 2 * pr;
            ull acc0 = 0ull, acc1 = 0ull;
            #pragma unroll
            for (int c2 = 0; c2 < 16; c2++) {
                ulonglong2 v = *reinterpret_cast<const ulonglong2*>(s_yc + c2 * 200 + y0);
                acc0 = f2fma(xc[c2], v.x, acc0);
                acc1 = f2fma(xc[c2], v.y, acc1);
            }
            float2 rr;
            rr.x = f2sum(acc0);
            rr.y = f2sum(acc1);
            *reinterpret_cast<float2*>(Sb + x * NPOS + y0) = rr;
        }
    }
}

// ---------------- Kernel B2: G[p,q] = 25-shift diagonal sum of S ----------------
__global__ __launch_bounds__(256) void k_gram_g() {
    int tid = threadIdx.x;
    int pt  = blockIdx.x;
    int b   = blockIdx.y;
    const float* Sb = g_S + b * (NPOS * NPOS);
    float* Gb = g_G + b * (PP * PP);

    #pragma unroll 1
    for (int idx = tid; idx < 25 * PP; idx += 256) {
        int p_l = idx / PP, q = idx - p_l * PP;
        int p  = pt * 25 + p_l;
        int pr = p / 10, pc = p - pr * 10;
        int qr = q / 10, qc = q - qr * 10;
        const float* s = Sb + (pr * 14 + pc) * NPOS + (qr * 14 + qc);
        float acc = 0.f;
        #pragma unroll
        for (int i = 0; i < KS; i++)
            #pragma unroll
            for (int j = 0; j < KS; j++)
                acc += __ldg(s + (i * 14 + j) * (NPOS + 1));
        Gb[p * PP + q] = acc;
    }
}

// ---------------- Kernel C1: expand Sigma_out off-diagonal rows (q != p) ----------------
__global__ __launch_bounds__(256) void k_expand_off(const float* __restrict__ w_sigma,
                                                    float* __restrict__ out) {
    __shared__ float  s_g[PP];
    __shared__ float4 s_sp[16];

    int tid = threadIdx.x;
    int p = blockIdx.x, b = blockIdx.y;
    int bp = b * PP + p;

    if (tid < PP) s_g[tid] = g_G[b * (PP * PP) + p * PP + tid];
    if (tid >= 128 && tid < 144) {
        int k4 = (tid - 128) * 4;
        float4 sp;
        sp.x = log1pf(expf(w_sigma[k4]));
        sp.y = log1pf(expf(w_sigma[k4 + 1]));
        sp.z = log1pf(expf(w_sigma[k4 + 2]));
        sp.w = log1pf(expf(w_sigma[k4 + 3]));
        s_sp[tid - 128] = sp;
    }
    __syncthreads();

    float* orow = out + BB * PP * KK + bp * (PP * KK);

    #pragma unroll
    for (int it = 0; it < 7; it++) {
        int v = tid + it * 256;
        if (v < PP * 16) {
            int q = v >> 4;
            if (q == p) continue;                    // diagonal row handled elsewhere
            int kc = v & 15, k4 = kc * 4;
            float g = s_g[q];
            float4 sp = s_sp[kc];
            float4 r;
            r.x = sp.x * g; r.y = sp.y * g; r.z = sp.z * g; r.w = sp.w * g;
            r.x = isfinite(r.x) ? r.x : 0.f;
            r.y = isfinite(r.y) ? r.y : 0.f;
            r.z = isfinite(r.z) ? r.z : 0.f;
            r.w = isfinite(r.w) ? r.w : 0.f;
            if (q == k4)     r.x = fabsf(r.x);
            if (q == k4 + 1) r.y = fabsf(r.y);
            if (q == k4 + 2) r.z = fabsf(r.z);
            if (q == k4 + 3) r.w = fabsf(r.w);
            *reinterpret_cast<float4*>(orow + 4 * v) = r;
        }
    }
}

// ---------------- Kernel C2: expand diagonal rows (q == p) ----------------
__global__ __launch_bounds__(256) void k_expand_diag(const float* __restrict__ w_sigma,
                                                     float* __restrict__ out) {
    int v = blockIdx.x * 256 + threadIdx.x;          // float4 index, 51200 total
    if (v >= BB * PP * 16) return;
    int bp = v >> 4, kc = v & 15, k4 = kc * 4;
    int b = bp / PP, p = bp - b * PP;

    float g = g_G[b * (PP * PP) + p * PP + p];
    float4 dv4 = *reinterpret_cast<const float4*>(g_dv + bp * KK + k4);
    float4 r;
    r.x = log1pf(expf(w_sigma[k4]))     * g + dv4.x;
    r.y = log1pf(expf(w_sigma[k4 + 1])) * g + dv4.y;
    r.z = log1pf(expf(w_sigma[k4 + 2])) * g + dv4.z;
    r.w = log1pf(expf(w_sigma[k4 + 3])) * g + dv4.w;
    r.x = isfinite(r.x) ? r.x : 0.f;
    r.y = isfinite(r.y) ? r.y : 0.f;
    r.z = isfinite(r.z) ? r.z : 0.f;
    r.w = isfinite(r.w) ? r.w : 0.f;
    if (p == k4)     r.x = fabsf(r.x);
    if (p == k4 + 1) r.y = fabsf(r.y);
    if (p == k4 + 2) r.z = fabsf(r.z);
    if (p == k4 + 3) r.w = fabsf(r.w);
    float* orow = out + BB * PP * KK + bp * (PP * KK) + p * KK;
    *reinterpret_cast<float4*>(orow + k4) = r;
}

// ---------------- launch ----------------
extern "C" void kernel_launch(void* const* d_in, const int* in_sizes, int n_in,
                              void* d_out, int out_size) {
    const float* mu_in    = (const float*)d_in[0];
    const float* Sigma_in = (const float*)d_in[1];
    const float* w_mu     = (const float*)d_in[2];
    const float* w_sigma  = (const float*)d_in[3];
    float* out = (float*)d_out;

    static cudaStream_t s2 = nullptr;
    static cudaEvent_t  eFork = nullptr, eJoin = nullptr;
    if (s2 == nullptr) {
        cudaStreamCreateWithFlags(&s2, cudaStreamNonBlocking);
        cudaEventCreateWithFlags(&eFork, cudaEventDisableTiming);
        cudaEventCreateWithFlags(&eJoin, cudaEventDisableTiming);
    }

    // side stream: Gram chain + off-diagonal Sigma expansion (no mu dependency)
    cudaEventRecord(eFork, 0);
    cudaStreamWaitEvent(s2, eFork, 0);
    k_gram_s<<<dim3(7, BB), 256, 0, s2>>>(mu_in);
    k_gram_g<<<dim3(4, BB), 256, 0, s2>>>();
    k_expand_off<<<dim3(PP, BB), 256, 0, s2>>>(w_sigma, out);
    cudaEventRecord(eJoin, s2);

    // main stream: mu path
    k_prep_w<<<100, 256>>>(w_mu);
    k_mu_diag<<<dim3(5, 4, BB), 160>>>(mu_in, Sigma_in, w_sigma, out);

    cudaStreamWaitEvent(0, eJoin, 0);
    k_expand_diag<<<200, 256>>>(w_sigma, out);
}

// round 14
// speedup vs baseline: 1.2627x; 1.1817x over previous
#include <cuda_runtime.h>
#include <cuda_bf16.h>
#include <math.h>

// Problem constants
#define BB   32
#define HH   14
#define WW   14
#define CC   32
#define KK   64
#define KS   5
#define OH   10
#define OW   10
#define PP   100      // OH*OW
#define NPOS 196      // H*W
#define MM   800      // KS*KS*C
#define IMG  6272     // NPOS*CC floats per batch
#define SIGB 1229312  // NPOS*NPOS*CC floats per batch of Sigma_in
#define SIGR 6304     // NPOS*CC + CC (diag row stride in floats)
#define PSTR 36       // padded smem stride per position (floats)

// Scratch (device globals)
// g_wt[((kq*25 + ij)*8 + c4)*16 + kkl] = {w[ij*32+4c4+0][k], w[+1][k], w[+2][k], w[+3][k]}, k = kq*16+kkl
__device__ float4 g_wt[4 * 25 * 8 * 16];   // 12800 float4 = 204.8 KB? no: 12800*16B = 204.8KB/4 = 51.2KB*4 = 204.8KB total, per-kq 51.2KB
__device__ float  g_dv[BB * PP * KK];      // diag_vals
__device__ float  g_G [BB * PP * PP];      // Gram matrices
__device__ float  g_S [BB * NPOS * NPOS];  // position-Gram S = X X^T (4.9 MB)

// ---------------- f32x2 packed helpers ----------------
typedef unsigned long long ull;

__device__ __forceinline__ ull f2fma(ull a, ull b, ull c) {
    ull d;
    asm("fma.rn.f32x2 %0, %1, %2, %3;" : "=l"(d) : "l"(a), "l"(b), "l"(c));
    return d;
}
__device__ __forceinline__ ull f2mul(ull a, ull b) {
    ull d;
    asm("mul.rn.f32x2 %0, %1, %2;" : "=l"(d) : "l"(a), "l"(b));
    return d;
}
__device__ __forceinline__ float f2sum(ull v) {
    float lo, hi;
    asm("mov.b64 {%0, %1}, %2;" : "=f"(lo), "=f"(hi) : "l"(v));
    return lo + hi;
}

// ---------------- Kernel 0: weight pack ----------------
// 12800 float4 elements, coalesced STG.128.
__global__ __launch_bounds__(256) void k_prep_w(const float* __restrict__ w_mu) {
    int idx = blockIdx.x * 256 + threadIdx.x;        // 0..12799
    if (idx >= 12800) return;
    int kq  = idx / 3200;
    int r   = idx - kq * 3200;
    int ij  = r >> 7;
    int rr  = r & 127;
    int c4  = rr >> 4;
    int kkl = rr & 15;
    int k   = kq * 16 + kkl;
    int bc  = ij * 32 + 4 * c4;
    float4 v;
    v.x = w_mu[(bc    ) * KK + k];
    v.y = w_mu[(bc + 1) * KK + k];
    v.z = w_mu[(bc + 2) * KK + k];
    v.w = w_mu[(bc + 3) * KK + k];
    g_wt[idx] = v;
}

// ---------------- Kernel A: mu_out + diag_vals ----------------
// grid (5 pt, 4 kq, 32 b) = 640 blocks, 160 threads (5 warps), 5 blocks/SM -> single wave.
// kk = tid&15, pg = tid>>4 (0..9) owns p_local = pg*2 + {0,1}.
// Weights staged per kernel-row (5 taps = 10KB), squares computed on the fly.
__global__ __launch_bounds__(160, 5) void k_mu_diag(const float* __restrict__ mu_in,
                                                    const float* __restrict__ Sg,
                                                    const float* __restrict__ w_sigma,
                                                    float* __restrict__ out_mu) {
    __shared__ __align__(16) float4 s_w [5 * 128];   // phase stage: [j(5)][c4(8)][kk(16)]
    __shared__ __align__(16) float  s_mu[84 * PSTR]; // 6 rows x 14 pos, padded
    __shared__ __align__(16) float  s_ds[84 * PSTR];
    __shared__ float s_S[84];
    __shared__ float s_tr[20];

    int tid = threadIdx.x;
    int pt  = blockIdx.x;            // output rows 2pt, 2pt+1
    int kq  = blockIdx.y;            // k quarter
    int b   = blockIdx.z;
    int kk  = tid & 15;
    int pg  = tid >> 4;              // 0..9

    const float4* wsrc = g_wt + kq * 3200;

    // --- prefetch phase 0 (kernel row 0: 640 float4) into registers ---
    float4 pf[4];
    #pragma unroll
    for (int l = 0; l < 4; l++)
        pf[l] = __ldg(wsrc + l * 160 + tid);

    // --- fused load: mu tile (6 image rows) + Sigma-diag gather + channel sums ---
    {
        const float4* msrc = reinterpret_cast<const float4*>(mu_in + b * IMG + pt * 28 * 32);
        const float*  sb   = Sg + b * SIGB;
        for (int t = tid; t < 672; t += 160) {
            int pos_l = t >> 3;                      // 0..83
            int c4    = t & 7;
            float4 mv = msrc[t];
            *reinterpret_cast<float4*>(s_mu + pos_l * PSTR + c4 * 4) = mv;
            int pos = pt * 28 + pos_l;
            float4 sg = *reinterpret_cast<const float4*>(sb + pos * SIGR + c4 * 4);
            *reinterpret_cast<float4*>(s_ds + pos_l * PSTR + c4 * 4) = sg;
            float part = sg.x + sg.y + sg.z + sg.w;
            part += __shfl_down_sync(0xffffffffu, part, 4, 8);
            part += __shfl_down_sync(0xffffffffu, part, 2, 8);
            part += __shfl_down_sync(0xffffffffu, part, 1, 8);
            if (c4 == 0) s_S[pos_l] = part;
        }
    }
    __syncthreads();

    // --- trace per patch (20 p's); consumed only after later syncs ---
    if (tid < 20) {
        int pr = tid / 10, pc = tid % 10;
        float s = 0.f;
        #pragma unroll
        for (int i = 0; i < KS; i++)
            #pragma unroll
            for (int j = 0; j < KS; j++)
                s += s_S[(pr + i) * 14 + pc + j];
        s_tr[tid] = s;
    }

    // p bases for this thread's 2 patches
    int pbase[2];
    #pragma unroll
    for (int jp = 0; jp < 2; jp++) {
        int pl = pg * 2 + jp;                        // 0..19
        int pr = pl / 10, pc = pl % 10;
        pbase[jp] = (pr * 14 + pc) * PSTR;
    }

    ull accM[2], accV[2];
    accM[0] = accM[1] = accV[0] = accV[1] = 0ull;

    const ulonglong2* s_w2 = reinterpret_cast<const ulonglong2*>(s_w);

    // --- 5 phases (kernel rows), 5 taps each ---
    #pragma unroll 1
    for (int i = 0; i < KS; i++) {
        // store stage i (registers -> smem), prefetch stage i+1
        #pragma unroll
        for (int l = 0; l < 4; l++)
            s_w[l * 160 + tid] = pf[l];
        if (i + 1 < KS) {
            const float4* ws = wsrc + (i + 1) * 640;
            #pragma unroll
            for (int l = 0; l < 4; l++)
                pf[l] = __ldg(ws + l * 160 + tid);
        }
        __syncthreads();                 // stage i visible

        int rowoff = i * 14 * PSTR;
        #pragma unroll
        for (int j = 0; j < KS; j++) {
            int sh = rowoff + j * PSTR;
            #pragma unroll
            for (int c4 = 0; c4 < 8; c4++) {
                ulonglong2 w = s_w2[(j * 8 + c4) * 16 + kk];   // {w pair ch 4c4..+1, w pair ch 4c4+2..+3}
                ull sA = f2mul(w.x, w.x);
                ull sB = f2mul(w.y, w.y);
                #pragma unroll
                for (int jp = 0; jp < 2; jp++) {
                    int off = pbase[jp] + sh + c4 * 4;
                    ulonglong2 a = *reinterpret_cast<const ulonglong2*>(s_mu + off);
                    ulonglong2 d = *reinterpret_cast<const ulonglong2*>(s_ds + off);
                    accM[jp] = f2fma(a.x, w.x, accM[jp]);
                    accM[jp] = f2fma(a.y, w.y, accM[jp]);
                    accV[jp] = f2fma(d.x, sA, accV[jp]);
                    accV[jp] = f2fma(d.y, sB, accV[jp]);
                }
            }
        }
        if (i + 1 < KS) __syncthreads(); // stage reads done before next overwrite
    }

    int kg = kq * 16 + kk;
    float spk = log1pf(expf(w_sigma[kg]));
    #pragma unroll
    for (int jp = 0; jp < 2; jp++) {
        int pl = pg * 2 + jp;
        int p  = pt * 20 + pl;
        int base = (b * PP + p) * KK + kg;
        out_mu[base] = f2sum(accM[jp]);
        g_dv[base]   = f2sum(accV[jp]) + spk * s_tr[pl];
    }
}

// ---------------- Kernel B1: S = X X^T (wide) ----------------
__global__ __launch_bounds__(256) void k_gram_s(const float* __restrict__ mu_in) {
    __shared__ __align__(16) float2 s_yc[16 * 200];   // [c2][pos], padded

    int tid = threadIdx.x;
    int b   = blockIdx.y;
    int x0  = blockIdx.x * 28;
    const float* mb = mu_in + b * IMG;

    for (int t = tid; t < 16 * NPOS; t += 256) {
        int c2 = t & 15, pos = t >> 4;
        s_yc[c2 * 200 + pos] = *reinterpret_cast<const float2*>(mb + pos * 32 + c2 * 2);
    }
    __syncthreads();

    int lane = tid & 31, wrp = tid >> 5;
    float* Sb = g_S + b * (NPOS * NPOS);

    #pragma unroll 1
    for (int r = 0; r < 4; r++) {
        int xl = wrp + 8 * r;
        if (xl >= 28) break;
        int x = x0 + xl;

        ull xc[16];
        #pragma unroll
        for (int c2 = 0; c2 < 16; c2++)
            xc[c2] = *reinterpret_cast<const ull*>(s_yc + c2 * 200 + x);   // broadcast

        #pragma unroll 1
        for (int m = 0; m < 4; m++) {
            int pr = lane + 32 * m;
            if (pr >= 98) break;
            int y0 = 2 * pr;
            ull acc0 = 0ull, acc1 = 0ull;
            #pragma unroll
            for (int c2 = 0; c2 < 16; c2++) {
                ulonglong2 v = *reinterpret_cast<const ulonglong2*>(s_yc + c2 * 200 + y0);
                acc0 = f2fma(xc[c2], v.x, acc0);
                acc1 = f2fma(xc[c2], v.y, acc1);
            }
            float2 rr;
            rr.x = f2sum(acc0);
            rr.y = f2sum(acc1);
            *reinterpret_cast<float2*>(Sb + x * NPOS + y0) = rr;
        }
    }
}

// ---------------- Kernel B2: G[p,q] = 25-shift diagonal sum of S ----------------
__global__ __launch_bounds__(256) void k_gram_g() {
    int tid = threadIdx.x;
    int pt  = blockIdx.x;
    int b   = blockIdx.y;
    const float* Sb = g_S + b * (NPOS * NPOS);
    float* Gb = g_G + b * (PP * PP);

    #pragma unroll 1
    for (int idx = tid; idx < 25 * PP; idx += 256) {
        int p_l = idx / PP, q = idx - p_l * PP;
        int p  = pt * 25 + p_l;
        int pr = p / 10, pc = p - pr * 10;
        int qr = q / 10, qc = q - qr * 10;
        const float* s = Sb + (pr * 14 + pc) * NPOS + (qr * 14 + qc);
        float acc = 0.f;
        #pragma unroll
        for (int i = 0; i < KS; i++)
            #pragma unroll
            for (int j = 0; j < KS; j++)
                acc += __ldg(s + (i * 14 + j) * (NPOS + 1));
        Gb[p * PP + q] = acc;
    }
}

// ---------------- Kernel C1: expand Sigma_out off-diagonal rows (q != p) ----------------
__global__ __launch_bounds__(256) void k_expand_off(const float* __restrict__ w_sigma,
                                                    float* __restrict__ out) {
    __shared__ float  s_g[PP];
    __shared__ float4 s_sp[16];

    int tid = threadIdx.x;
    int p = blockIdx.x, b = blockIdx.y;
    int bp = b * PP + p;

    if (tid < PP) s_g[tid] = g_G[b * (PP * PP) + p * PP + tid];
    if (tid >= 128 && tid < 144) {
        int k4 = (tid - 128) * 4;
        float4 sp;
        sp.x = log1pf(expf(w_sigma[k4]));
        sp.y = log1pf(expf(w_sigma[k4 + 1]));
        sp.z = log1pf(expf(w_sigma[k4 + 2]));
        sp.w = log1pf(expf(w_sigma[k4 + 3]));
        s_sp[tid - 128] = sp;
    }
    __syncthreads();

    float* orow = out + BB * PP * KK + bp * (PP * KK);

    #pragma unroll
    for (int it = 0; it < 7; it++) {
        int v = tid + it * 256;
        if (v < PP * 16) {
            int q = v >> 4;
            if (q == p) continue;                    // diagonal row handled elsewhere
            int kc = v & 15, k4 = kc * 4;
            float g = s_g[q];
            float4 sp = s_sp[kc];
            float4 r;
            r.x = sp.x * g; r.y = sp.y * g; r.z = sp.z * g; r.w = sp.w * g;
            r.x = isfinite(r.x) ? r.x : 0.f;
            r.y = isfinite(r.y) ? r.y : 0.f;
            r.z = isfinite(r.z) ? r.z : 0.f;
            r.w = isfinite(r.w) ? r.w : 0.f;
            if (q == k4)     r.x = fabsf(r.x);
            if (q == k4 + 1) r.y = fabsf(r.y);
            if (q == k4 + 2) r.z = fabsf(r.z);
            if (q == k4 + 3) r.w = fabsf(r.w);
            *reinterpret_cast<float4*>(orow + 4 * v) = r;
        }
    }
}

// ---------------- Kernel C2: expand diagonal rows (q == p) ----------------
__global__ __launch_bounds__(256) void k_expand_diag(const float* __restrict__ w_sigma,
                                                     float* __restrict__ out) {
    int v = blockIdx.x * 256 + threadIdx.x;          // float4 index, 51200 total
    if (v >= BB * PP * 16) return;
    int bp = v >> 4, kc = v & 15, k4 = kc * 4;
    int b = bp / PP, p = bp - b * PP;

    float g = g_G[b * (PP * PP) + p * PP + p];
    float4 dv4 = *reinterpret_cast<const float4*>(g_dv + bp * KK + k4);
    float4 r;
    r.x = log1pf(expf(w_sigma[k4]))     * g + dv4.x;
    r.y = log1pf(expf(w_sigma[k4 + 1])) * g + dv4.y;
    r.z = log1pf(expf(w_sigma[k4 + 2])) * g + dv4.z;
    r.w = log1pf(expf(w_sigma[k4 + 3])) * g + dv4.w;
    r.x = isfinite(r.x) ? r.x : 0.f;
    r.y = isfinite(r.y) ? r.y : 0.f;
    r.z = isfinite(r.z) ? r.z : 0.f;
    r.w = isfinite(r.w) ? r.w : 0.f;
    if (p == k4)     r.x = fabsf(r.x);
    if (p == k4 + 1) r.y = fabsf(r.y);
    if (p == k4 + 2) r.z = fabsf(r.z);
    if (p == k4 + 3) r.w = fabsf(r.w);
    float* orow = out + BB * PP * KK + bp * (PP * KK) + p * KK;
    *reinterpret_cast<float4*>(orow + k4) = r;
}

// ---------------- launch ----------------
extern "C" void kernel_launch(void* const* d_in, const int* in_sizes, int n_in,
                              void* d_out, int out_size) {
    const float* mu_in    = (const float*)d_in[0];
    const float* Sigma_in = (const float*)d_in[1];
    const float* w_mu     = (const float*)d_in[2];
    const float* w_sigma  = (const float*)d_in[3];
    float* out = (float*)d_out;

    static cudaStream_t s2 = nullptr;
    static cudaEvent_t  eFork = nullptr, eJoin = nullptr;
    if (s2 == nullptr) {
        cudaStreamCreateWithFlags(&s2, cudaStreamNonBlocking);
        cudaEventCreateWithFlags(&eFork, cudaEventDisableTiming);
        cudaEventCreateWithFlags(&eJoin, cudaEventDisableTiming);
    }

    // side stream: Gram chain + off-diagonal Sigma expansion (no mu dependency)
    cudaEventRecord(eFork, 0);
    cudaStreamWaitEvent(s2, eFork, 0);
    k_gram_s<<<dim3(7, BB), 256, 0, s2>>>(mu_in);
    k_gram_g<<<dim3(4, BB), 256, 0, s2>>>();
    k_expand_off<<<dim3(PP, BB), 256, 0, s2>>>(w_sigma, out);
    cudaEventRecord(eJoin, s2);

    // main stream: mu path
    k_prep_w<<<50, 256>>>(w_mu);
    k_mu_diag<<<dim3(5, 4, BB), 160>>>(mu_in, Sigma_in, w_sigma, out);

    cudaStreamWaitEvent(0, eJoin, 0);
    k_expand_diag<<<200, 256>>>(w_sigma, out);
}

// round 15
// speedup vs baseline: 1.3332x; 1.0558x over previous
#include <cuda_runtime.h>
#include <cuda_bf16.h>
#include <math.h>

// Problem constants
#define BB   32
#define HH   14
#define WW   14
#define CC   32
#define KK   64
#define KS   5
#define OH   10
#define OW   10
#define PP   100      // OH*OW
#define NPOS 196      // H*W
#define MM   800      // KS*KS*C
#define IMG  6272     // NPOS*CC floats per batch
#define SIGB 1229312  // NPOS*NPOS*CC floats per batch of Sigma_in
#define SIGR 6304     // NPOS*CC + CC (diag row stride in floats)
#define PSTR 36       // padded smem stride per position (floats)

// Scratch (device globals)
// g_wt float4 layout: [(kh*25 + ij)*256 + c4*32 + k2*16 + kk]
//   value = {w[ij*32+4c4+0][k], w[+1][k], w[+2][k], w[+3][k]}, k = kh*32 + k2*16 + kk
__device__ float4 g_wt[2 * 25 * 256];      // 12800 float4 = 204.8 KB
__device__ float  g_dv[BB * PP * KK];      // diag_vals
__device__ float  g_G [BB * PP * PP];      // Gram matrices
__device__ float  g_S [BB * NPOS * NPOS];  // position-Gram S = X X^T (4.9 MB)

// ---------------- f32x2 packed helpers ----------------
typedef unsigned long long ull;

__device__ __forceinline__ ull f2fma(ull a, ull b, ull c) {
    ull d;
    asm("fma.rn.f32x2 %0, %1, %2, %3;" : "=l"(d) : "l"(a), "l"(b), "l"(c));
    return d;
}
__device__ __forceinline__ ull f2mul(ull a, ull b) {
    ull d;
    asm("mul.rn.f32x2 %0, %1, %2;" : "=l"(d) : "l"(a), "l"(b));
    return d;
}
__device__ __forceinline__ float f2sum(ull v) {
    float lo, hi;
    asm("mov.b64 {%0, %1}, %2;" : "=f"(lo), "=f"(hi) : "l"(v));
    return lo + hi;
}

// ---------------- Kernel 0: weight pack (coalesced via smem tile) ----------------
// One block per ij. Loads 32x64 w_mu tile coalesced, writes 512 float4 coalesced.
__global__ __launch_bounds__(256) void k_prep_w(const float* __restrict__ w_mu) {
    __shared__ float s_t[32 * 65];                   // [c][k], padded
    int tid = threadIdx.x;
    int ij  = blockIdx.x;

    // coalesced load: 2048 floats = 512 float4
    const float4* src = reinterpret_cast<const float4*>(w_mu + ij * 32 * KK);
    #pragma unroll
    for (int l = 0; l < 2; l++) {
        int f = tid + l * 256;                       // 0..511
        int c = f >> 4, kq4 = f & 15;
        float4 v = src[f];
        s_t[c * 65 + kq4 * 4    ] = v.x;
        s_t[c * 65 + kq4 * 4 + 1] = v.y;
        s_t[c * 65 + kq4 * 4 + 2] = v.z;
        s_t[c * 65 + kq4 * 4 + 3] = v.w;
    }
    __syncthreads();

    // write 512 float4 (channel-quad gather), coalesced in g_wt
    #pragma unroll
    for (int l = 0; l < 2; l++) {
        int o  = tid + l * 256;                      // 0..511
        int kh = o >> 8;
        int rr = o & 255;
        int c4 = rr >> 5;
        int kx = rr & 31;                            // k2*16 + kk
        int k  = kh * 32 + kx;
        float4 v;
        v.x = s_t[(4 * c4    ) * 65 + k];
        v.y = s_t[(4 * c4 + 1) * 65 + k];
        v.z = s_t[(4 * c4 + 2) * 65 + k];
        v.w = s_t[(4 * c4 + 3) * 65 + k];
        g_wt[(kh * 25 + ij) * 256 + c4 * 32 + kx] = v;
    }
}

// ---------------- Kernel A: mu_out + diag_vals ----------------
// grid (5 pt, 2 kh, 32 b) = 320 blocks, 160 threads (5 warps), all resident (1 wave).
// kk = tid&15, pg = tid>>4 (0..9): thread owns p = {2pg, 2pg+1} and k = {kh*32+kk, kh*32+16+kk}.
// Weights staged per kernel-row i (5 taps = 20KB), squares on the fly.
__global__ __launch_bounds__(160, 3) void k_mu_diag(const float* __restrict__ mu_in,
                                                    const float* __restrict__ Sg,
                                                    const float* __restrict__ w_sigma,
                                                    float* __restrict__ out_mu) {
    __shared__ __align__(16) float4 s_w [5 * 256];   // [j(5)][c4(8)][k2(2)][kk(16)]
    __shared__ __align__(16) float  s_mu[84 * PSTR]; // 6 rows x 14 pos, padded
    __shared__ __align__(16) float  s_ds[84 * PSTR];
    __shared__ float s_S[84];
    __shared__ float s_tr[20];

    int tid = threadIdx.x;
    int pt  = blockIdx.x;            // output rows 2pt, 2pt+1
    int kh  = blockIdx.y;            // k half
    int b   = blockIdx.z;
    int kk  = tid & 15;
    int pg  = tid >> 4;              // 0..9

    const float4* wsrc = g_wt + kh * 25 * 256;       // this k-half's table

    // --- prefetch phase 0 (kernel row 0: 1280 float4) into registers ---
    float4 pf[8];
    #pragma unroll
    for (int l = 0; l < 8; l++)
        pf[l] = __ldg(wsrc + l * 160 + tid);

    // --- fused load: mu tile (6 image rows) + Sigma-diag gather + channel sums ---
    {
        const float4* msrc = reinterpret_cast<const float4*>(mu_in + b * IMG + pt * 28 * 32);
        const float*  sb   = Sg + b * SIGB;
        for (int t = tid; t < 672; t += 160) {
            int pos_l = t >> 3;                      // 0..83
            int c4    = t & 7;
            float4 mv = msrc[t];
            *reinterpret_cast<float4*>(s_mu + pos_l * PSTR + c4 * 4) = mv;
            int pos = pt * 28 + pos_l;
            float4 sg = *reinterpret_cast<const float4*>(sb + pos * SIGR + c4 * 4);
            *reinterpret_cast<float4*>(s_ds + pos_l * PSTR + c4 * 4) = sg;
            float part = sg.x + sg.y + sg.z + sg.w;
            part += __shfl_down_sync(0xffffffffu, part, 4, 8);
            part += __shfl_down_sync(0xffffffffu, part, 2, 8);
            part += __shfl_down_sync(0xffffffffu, part, 1, 8);
            if (c4 == 0) s_S[pos_l] = part;
        }
    }
    __syncthreads();

    // --- trace per patch (20 p's) ---
    if (tid < 20) {
        int pr = tid / 10, pc = tid % 10;
        float s = 0.f;
        #pragma unroll
        for (int i = 0; i < KS; i++)
            #pragma unroll
            for (int j = 0; j < KS; j++)
                s += s_S[(pr + i) * 14 + pc + j];
        s_tr[tid] = s;
    }

    // p bases for this thread's 2 patches
    int pbase[2];
    #pragma unroll
    for (int jp = 0; jp < 2; jp++) {
        int pl = pg * 2 + jp;                        // 0..19
        int pr = pl / 10, pc = pl % 10;
        pbase[jp] = (pr * 14 + pc) * PSTR;
    }

    ull accM[2][2], accV[2][2];
    #pragma unroll
    for (int jp = 0; jp < 2; jp++) {
        accM[jp][0] = 0ull; accM[jp][1] = 0ull;
        accV[jp][0] = 0ull; accV[jp][1] = 0ull;
    }

    const ulonglong2* s_w2 = reinterpret_cast<const ulonglong2*>(s_w);

    // --- 5 phases (kernel rows), 5 taps each ---
    #pragma unroll 1
    for (int i = 0; i < KS; i++) {
        // store stage i, prefetch stage i+1
        #pragma unroll
        for (int l = 0; l < 8; l++)
            s_w[l * 160 + tid] = pf[l];
        if (i + 1 < KS) {
            const float4* ws = wsrc + (i + 1) * 1280;
            #pragma unroll
            for (int l = 0; l < 8; l++)
                pf[l] = __ldg(ws + l * 160 + tid);
        }
        __syncthreads();                 // stage i visible

        int rowoff = i * 14 * PSTR;
        #pragma unroll
        for (int j = 0; j < KS; j++) {
            int sh = rowoff + j * PSTR;
            #pragma unroll
            for (int c4 = 0; c4 < 8; c4++) {
                // weights: k2=0 and k2=1, each {ch pair 0-1, ch pair 2-3}
                ulonglong2 w0 = s_w2[(j * 8 + c4) * 32 + kk];        // k = kh*32 + kk
                ulonglong2 w1 = s_w2[(j * 8 + c4) * 32 + 16 + kk];   // k = kh*32 + 16 + kk
                ull s0A = f2mul(w0.x, w0.x);
                ull s0B = f2mul(w0.y, w0.y);
                ull s1A = f2mul(w1.x, w1.x);
                ull s1B = f2mul(w1.y, w1.y);
                #pragma unroll
                for (int jp = 0; jp < 2; jp++) {
                    int off = pbase[jp] + sh + c4 * 4;
                    ulonglong2 a = *reinterpret_cast<const ulonglong2*>(s_mu + off);
                    ulonglong2 d = *reinterpret_cast<const ulonglong2*>(s_ds + off);
                    accM[jp][0] = f2fma(a.x, w0.x, accM[jp][0]);
                    accM[jp][0] = f2fma(a.y, w0.y, accM[jp][0]);
                    accM[jp][1] = f2fma(a.x, w1.x, accM[jp][1]);
                    accM[jp][1] = f2fma(a.y, w1.y, accM[jp][1]);
                    accV[jp][0] = f2fma(d.x, s0A, accV[jp][0]);
                    accV[jp][0] = f2fma(d.y, s0B, accV[jp][0]);
                    accV[jp][1] = f2fma(d.x, s1A, accV[jp][1]);
                    accV[jp][1] = f2fma(d.y, s1B, accV[jp][1]);
                }
            }
        }
        if (i + 1 < KS) __syncthreads(); // stage reads done before next overwrite
    }

    int kg0 = kh * 32 + kk;
    int kg1 = kh * 32 + 16 + kk;
    float sp0 = log1pf(expf(w_sigma[kg0]));
    float sp1 = log1pf(expf(w_sigma[kg1]));
    #pragma unroll
    for (int jp = 0; jp < 2; jp++) {
        int pl = pg * 2 + jp;
        int p  = pt * 20 + pl;
        int base = (b * PP + p) * KK;
        float tr = s_tr[pl];
        out_mu[base + kg0] = f2sum(accM[jp][0]);
        out_mu[base + kg1] = f2sum(accM[jp][1]);
        g_dv[base + kg0]   = f2sum(accV[jp][0]) + sp0 * tr;
        g_dv[base + kg1]   = f2sum(accV[jp][1]) + sp1 * tr;
    }
}

// ---------------- Kernel B1: S = X X^T (wide) ----------------
__global__ __launch_bounds__(256) void k_gram_s(const float* __restrict__ mu_in) {
    __shared__ __align__(16) float2 s_yc[16 * 200];   // [c2][pos], padded

    int tid = threadIdx.x;
    int b   = blockIdx.y;
    int x0  = blockIdx.x * 28;
    const float* mb = mu_in + b * IMG;

    for (int t = tid; t < 16 * NPOS; t += 256) {
        int c2 = t & 15, pos = t >> 4;
        s_yc[c2 * 200 + pos] = *reinterpret_cast<const float2*>(mb + pos * 32 + c2 * 2);
    }
    __syncthreads();

    int lane = tid & 31, wrp = tid >> 5;
    float* Sb = g_S + b * (NPOS * NPOS);

    #pragma unroll 1
    for (int r = 0; r < 4; r++) {
        int xl = wrp + 8 * r;
        if (xl >= 28) break;
        int x = x0 + xl;

        ull xc[16];
        #pragma unroll
        for (int c2 = 0; c2 < 16; c2++)
            xc[c2] = *reinterpret_cast<const ull*>(s_yc + c2 * 200 + x);   // broadcast

        #pragma unroll 1
        for (int m = 0; m < 4; m++) {
            int pr = lane + 32 * m;
            if (pr >= 98) break;
            int y0 = 2 * pr;
            ull acc0 = 0ull, acc1 = 0ull;
            #pragma unroll
            for (int c2 = 0; c2 < 16; c2++) {
                ulonglong2 v = *reinterpret_cast<const ulonglong2*>(s_yc + c2 * 200 + y0);
                acc0 = f2fma(xc[c2], v.x, acc0);
                acc1 = f2fma(xc[c2], v.y, acc1);
            }
            float2 rr;
            rr.x = f2sum(acc0);
            rr.y = f2sum(acc1);
            *reinterpret_cast<float2*>(Sb + x * NPOS + y0) = rr;
        }
    }
}

// ---------------- Kernel B2: G[p,q] = 25-shift diagonal sum of S ----------------
__global__ __launch_bounds__(256) void k_gram_g() {
    int tid = threadIdx.x;
    int pt  = blockIdx.x;
    int b   = blockIdx.y;
    const float* Sb = g_S + b * (NPOS * NPOS);
    float* Gb = g_G + b * (PP * PP);

    #pragma unroll 1
    for (int idx = tid; idx < 25 * PP; idx += 256) {
        int p_l = idx / PP, q = idx - p_l * PP;
        int p  = pt * 25 + p_l;
        int pr = p / 10, pc = p - pr * 10;
        int qr = q / 10, qc = q - qr * 10;
        const float* s = Sb + (pr * 14 + pc) * NPOS + (qr * 14 + qc);
        float acc = 0.f;
        #pragma unroll
        for (int i = 0; i < KS; i++)
            #pragma unroll
            for (int j = 0; j < KS; j++)
                acc += __ldg(s + (i * 14 + j) * (NPOS + 1));
        Gb[p * PP + q] = acc;
    }
}

// ---------------- Kernel C1: expand Sigma_out off-diagonal rows (q != p) ----------------
__global__ __launch_bounds__(256) void k_expand_off(const float* __restrict__ w_sigma,
                                                    float* __restrict__ out) {
    __shared__ float  s_g[PP];
    __shared__ float4 s_sp[16];

    int tid = threadIdx.x;
    int p = blockIdx.x, b = blockIdx.y;
    int bp = b * PP + p;

    if (tid < PP) s_g[tid] = g_G[b * (PP * PP) + p * PP + tid];
    if (tid >= 128 && tid < 144) {
        int k4 = (tid - 128) * 4;
        float4 sp;
        sp.x = log1pf(expf(w_sigma[k4]));
        sp.y = log1pf(expf(w_sigma[k4 + 1]));
        sp.z = log1pf(expf(w_sigma[k4 + 2]));
        sp.w = log1pf(expf(w_sigma[k4 + 3]));
        s_sp[tid - 128] = sp;
    }
    __syncthreads();

    float* orow = out + BB * PP * KK + bp * (PP * KK);

    #pragma unroll
    for (int it = 0; it < 7; it++) {
        int v = tid + it * 256;
        if (v < PP * 16) {
            int q = v >> 4;
            if (q == p) continue;                    // diagonal row handled elsewhere
            int kc = v & 15, k4 = kc * 4;
            float g = s_g[q];
            float4 sp = s_sp[kc];
            float4 r;
            r.x = sp.x * g; r.y = sp.y * g; r.z = sp.z * g; r.w = sp.w * g;
            r.x = isfinite(r.x) ? r.x : 0.f;
            r.y = isfinite(r.y) ? r.y : 0.f;
            r.z = isfinite(r.z) ? r.z : 0.f;
            r.w = isfinite(r.w) ? r.w : 0.f;
            if (q == k4)     r.x = fabsf(r.x);
            if (q == k4 + 1) r.y = fabsf(r.y);
            if (q == k4 + 2) r.z = fabsf(r.z);
            if (q == k4 + 3) r.w = fabsf(r.w);
            *reinterpret_cast<float4*>(orow + 4 * v) = r;
        }
    }
}

// ---------------- Kernel C2: expand diagonal rows (q == p) ----------------
__global__ __launch_bounds__(256) void k_expand_diag(const float* __restrict__ w_sigma,
                                                     float* __restrict__ out) {
    int v = blockIdx.x * 256 + threadIdx.x;          // float4 index, 51200 total
    if (v >= BB * PP * 16) return;
    int bp = v >> 4, kc = v & 15, k4 = kc * 4;
    int b = bp / PP, p = bp - b * PP;

    float g = g_G[b * (PP * PP) + p * PP + p];
    float4 dv4 = *reinterpret_cast<const float4*>(g_dv + bp * KK + k4);
    float4 r;
    r.x = log1pf(expf(w_sigma[k4]))     * g + dv4.x;
    r.y = log1pf(expf(w_sigma[k4 + 1])) * g + dv4.y;
    r.z = log1pf(expf(w_sigma[k4 + 2])) * g + dv4.z;
    r.w = log1pf(expf(w_sigma[k4 + 3])) * g + dv4.w;
    r.x = isfinite(r.x) ? r.x : 0.f;
    r.y = isfinite(r.y) ? r.y : 0.f;
    r.z = isfinite(r.z) ? r.z : 0.f;
    r.w = isfinite(r.w) ? r.w : 0.f;
    if (p == k4)     r.x = fabsf(r.x);
    if (p == k4 + 1) r.y = fabsf(r.y);
    if (p == k4 + 2) r.z = fabsf(r.z);
    if (p == k4 + 3) r.w = fabsf(r.w);
    float* orow = out + BB * PP * KK + bp * (PP * KK) + p * KK;
    *reinterpret_cast<float4*>(orow + k4) = r;
}

// ---------------- launch ----------------
extern "C" void kernel_launch(void* const* d_in, const int* in_sizes, int n_in,
                              void* d_out, int out_size) {
    const float* mu_in    = (const float*)d_in[0];
    const float* Sigma_in = (const float*)d_in[1];
    const float* w_mu     = (const float*)d_in[2];
    const float* w_sigma  = (const float*)d_in[3];
    float* out = (float*)d_out;

    static cudaStream_t s2 = nullptr;
    static cudaEvent_t  eFork = nullptr, eJoin = nullptr;
    if (s2 == nullptr) {
        cudaStreamCreateWithFlags(&s2, cudaStreamNonBlocking);
        cudaEventCreateWithFlags(&eFork, cudaEventDisableTiming);
        cudaEventCreateWithFlags(&eJoin, cudaEventDisableTiming);
    }

    // side stream: Gram chain + off-diagonal Sigma expansion (no mu dependency)
    cudaEventRecord(eFork, 0);
    cudaStreamWaitEvent(s2, eFork, 0);
    k_gram_s<<<dim3(7, BB), 256, 0, s2>>>(mu_in);
    k_gram_g<<<dim3(4, BB), 256, 0, s2>>>();
    k_expand_off<<<dim3(PP, BB), 256, 0, s2>>>(w_sigma, out);
    cudaEventRecord(eJoin, s2);

    // main stream: mu path
    k_prep_w<<<25, 256>>>(w_mu);
    k_mu_diag<<<dim3(5, 2, BB), 160>>>(mu_in, Sigma_in, w_sigma, out);

    cudaStreamWaitEvent(0, eJoin, 0);
    k_expand_diag<<<200, 256>>>(w_sigma, out);
}

// round 16
// speedup vs baseline: 1.3688x; 1.0268x over previous
#include <cuda_runtime.h>
#include <cuda_bf16.h>
#include <math.h>

// Problem constants
#define BB   32
#define HH   14
#define WW   14
#define CC   32
#define KK   64
#define KS   5
#define OH   10
#define OW   10
#define PP   100      // OH*OW
#define NPOS 196      // H*W
#define MM   800      // KS*KS*C
#define IMG  6272     // NPOS*CC floats per batch
#define SIGB 1229312  // NPOS*NPOS*CC floats per batch of Sigma_in
#define SIGR 6304     // NPOS*CC + CC (diag row stride in floats)
#define PSTR 36       // padded smem stride per position (floats)

// Scratch (device globals)
__device__ float g_dv[BB * PP * KK];       // diag_vals
__device__ float g_S [BB * NPOS * NPOS];   // position-Gram S = X X^T (4.9 MB)

// ---------------- f32x2 packed helpers ----------------
typedef unsigned long long ull;

__device__ __forceinline__ ull f2fma(ull a, ull b, ull c) {
    ull d;
    asm("fma.rn.f32x2 %0, %1, %2, %3;" : "=l"(d) : "l"(a), "l"(b), "l"(c));
    return d;
}
__device__ __forceinline__ ull f2mul(ull a, ull b) {
    ull d;
    asm("mul.rn.f32x2 %0, %1, %2;" : "=l"(d) : "l"(a), "l"(b));
    return d;
}
__device__ __forceinline__ float f2sum(ull v) {
    float lo, hi;
    asm("mov.b64 {%0, %1}, %2;" : "=f"(lo), "=f"(hi) : "l"(v));
    return lo + hi;
}

// ---------------- Kernel A: mu_out + diag_vals ----------------
// grid (5 pt, 2 kh, 32 b) = 320 blocks, 160 threads (5 warps), single wave.
// kk = tid&15, pg = tid>>4 (0..9): thread owns p = {2pg, 2pg+1}, k = {kh*32+kk, kh*32+16+kk}.
// Weights loaded directly from w_mu (channel-quad gather) per kernel-row phase.
__global__ __launch_bounds__(160, 3) void k_mu_diag(const float* __restrict__ mu_in,
                                                    const float* __restrict__ Sg,
                                                    const float* __restrict__ w_mu,
                                                    const float* __restrict__ w_sigma,
                                                    float* __restrict__ out_mu) {
    __shared__ __align__(16) float4 s_w [5 * 256];   // [j(5)][c4(8)][k2(2)][kk(16)]
    __shared__ __align__(16) float  s_mu[84 * PSTR]; // 6 rows x 14 pos, padded
    __shared__ __align__(16) float  s_ds[84 * PSTR];
    __shared__ float s_S[84];
    __shared__ float s_tr[20];

    int tid = threadIdx.x;
    int pt  = blockIdx.x;            // output rows 2pt, 2pt+1
    int kh  = blockIdx.y;            // k half
    int b   = blockIdx.z;
    int kk  = tid & 15;
    int pg  = tid >> 4;              // 0..9

    // per-thread weight gather indices (f = l*160 + tid -> j, c4, kx)
    // pf[l] = {w_mu[(bc)*64+k], w_mu[(bc+1)*64+k], w_mu[(bc+2)*64+k], w_mu[(bc+3)*64+k]}
    // with j = f>>8, rr = f&255, c4 = rr>>5, kx = rr&31, k = kh*32+kx, bc = (i*5+j)*32+4*c4
    float4 pf[8];

    // --- prefetch phase 0 (kernel row i=0) directly from w_mu ---
    #pragma unroll
    for (int l = 0; l < 8; l++) {
        int f  = l * 160 + tid;
        int j  = f >> 8;
        int rr = f & 255;
        int c4 = rr >> 5;
        int kx = rr & 31;
        const float* wp = w_mu + ((j * 32 + 4 * c4) * KK) + kh * 32 + kx;
        pf[l].x = __ldg(wp);
        pf[l].y = __ldg(wp + KK);
        pf[l].z = __ldg(wp + 2 * KK);
        pf[l].w = __ldg(wp + 3 * KK);
    }

    // --- fused load: mu tile (6 image rows) + Sigma-diag gather + channel sums ---
    {
        const float4* msrc = reinterpret_cast<const float4*>(mu_in + b * IMG + pt * 28 * 32);
        const float*  sb   = Sg + b * SIGB;
        for (int t = tid; t < 672; t += 160) {
            int pos_l = t >> 3;                      // 0..83
            int c4    = t & 7;
            float4 mv = msrc[t];
            *reinterpret_cast<float4*>(s_mu + pos_l * PSTR + c4 * 4) = mv;
            int pos = pt * 28 + pos_l;
            float4 sg = *reinterpret_cast<const float4*>(sb + pos * SIGR + c4 * 4);
            *reinterpret_cast<float4*>(s_ds + pos_l * PSTR + c4 * 4) = sg;
            float part = sg.x + sg.y + sg.z + sg.w;
            part += __shfl_down_sync(0xffffffffu, part, 4, 8);
            part += __shfl_down_sync(0xffffffffu, part, 2, 8);
            part += __shfl_down_sync(0xffffffffu, part, 1, 8);
            if (c4 == 0) s_S[pos_l] = part;
        }
    }
    __syncthreads();

    // --- trace per patch (20 p's) ---
    if (tid < 20) {
        int pr = tid / 10, pc = tid % 10;
        float s = 0.f;
        #pragma unroll
        for (int i = 0; i < KS; i++)
            #pragma unroll
            for (int j = 0; j < KS; j++)
                s += s_S[(pr + i) * 14 + pc + j];
        s_tr[tid] = s;
    }

    // p bases for this thread's 2 patches
    int pbase[2];
    #pragma unroll
    for (int jp = 0; jp < 2; jp++) {
        int pl = pg * 2 + jp;                        // 0..19
        int pr = pl / 10, pc = pl % 10;
        pbase[jp] = (pr * 14 + pc) * PSTR;
    }

    ull accM[2][2], accV[2][2];
    #pragma unroll
    for (int jp = 0; jp < 2; jp++) {
        accM[jp][0] = 0ull; accM[jp][1] = 0ull;
        accV[jp][0] = 0ull; accV[jp][1] = 0ull;
    }

    const ulonglong2* s_w2 = reinterpret_cast<const ulonglong2*>(s_w);

    // --- 5 phases (kernel rows), 5 taps each ---
    #pragma unroll 1
    for (int i = 0; i < KS; i++) {
        // store stage i, prefetch stage i+1 from w_mu
        #pragma unroll
        for (int l = 0; l < 8; l++)
            s_w[l * 160 + tid] = pf[l];
        if (i + 1 < KS) {
            const float* wrow = w_mu + (i + 1) * 5 * 32 * KK + kh * 32;
            #pragma unroll
            for (int l = 0; l < 8; l++) {
                int f  = l * 160 + tid;
                int j  = f >> 8;
                int rr = f & 255;
                int c4 = rr >> 5;
                int kx = rr & 31;
                const float* wp = wrow + (j * 32 + 4 * c4) * KK + kx;
                pf[l].x = __ldg(wp);
                pf[l].y = __ldg(wp + KK);
                pf[l].z = __ldg(wp + 2 * KK);
                pf[l].w = __ldg(wp + 3 * KK);
            }
        }
        __syncthreads();                 // stage i visible

        int rowoff = i * 14 * PSTR;
        #pragma unroll
        for (int j = 0; j < KS; j++) {
            int sh = rowoff + j * PSTR;
            #pragma unroll
            for (int c4 = 0; c4 < 8; c4++) {
                ulonglong2 w0 = s_w2[(j * 8 + c4) * 32 + kk];        // k = kh*32 + kk
                ulonglong2 w1 = s_w2[(j * 8 + c4) * 32 + 16 + kk];   // k = kh*32 + 16 + kk
                ull s0A = f2mul(w0.x, w0.x);
                ull s0B = f2mul(w0.y, w0.y);
                ull s1A = f2mul(w1.x, w1.x);
                ull s1B = f2mul(w1.y, w1.y);
                #pragma unroll
                for (int jp = 0; jp < 2; jp++) {
                    int off = pbase[jp] + sh + c4 * 4;
                    ulonglong2 a = *reinterpret_cast<const ulonglong2*>(s_mu + off);
                    ulonglong2 d = *reinterpret_cast<const ulonglong2*>(s_ds + off);
                    accM[jp][0] = f2fma(a.x, w0.x, accM[jp][0]);
                    accM[jp][0] = f2fma(a.y, w0.y, accM[jp][0]);
                    accM[jp][1] = f2fma(a.x, w1.x, accM[jp][1]);
                    accM[jp][1] = f2fma(a.y, w1.y, accM[jp][1]);
                    accV[jp][0] = f2fma(d.x, s0A, accV[jp][0]);
                    accV[jp][0] = f2fma(d.y, s0B, accV[jp][0]);
                    accV[jp][1] = f2fma(d.x, s1A, accV[jp][1]);
                    accV[jp][1] = f2fma(d.y, s1B, accV[jp][1]);
                }
            }
        }
        if (i + 1 < KS) __syncthreads(); // stage reads done before next overwrite
    }

    int kg0 = kh * 32 + kk;
    int kg1 = kh * 32 + 16 + kk;
    float sp0 = log1pf(expf(w_sigma[kg0]));
    float sp1 = log1pf(expf(w_sigma[kg1]));
    #pragma unroll
    for (int jp = 0; jp < 2; jp++) {
        int pl = pg * 2 + jp;
        int p  = pt * 20 + pl;
        int base = (b * PP + p) * KK;
        float tr = s_tr[pl];
        out_mu[base + kg0] = f2sum(accM[jp][0]);
        out_mu[base + kg1] = f2sum(accM[jp][1]);
        g_dv[base + kg0]   = f2sum(accV[jp][0]) + sp0 * tr;
        g_dv[base + kg1]   = f2sum(accV[jp][1]) + sp1 * tr;
    }
}

// ---------------- Kernel B: S = X X^T (wide) ----------------
__global__ __launch_bounds__(256) void k_gram_s(const float* __restrict__ mu_in) {
    __shared__ __align__(16) float2 s_yc[16 * 200];   // [c2][pos], padded

    int tid = threadIdx.x;
    int b   = blockIdx.y;
    int x0  = blockIdx.x * 28;
    const float* mb = mu_in + b * IMG;

    for (int t = tid; t < 16 * NPOS; t += 256) {
        int c2 = t & 15, pos = t >> 4;
        s_yc[c2 * 200 + pos] = *reinterpret_cast<const float2*>(mb + pos * 32 + c2 * 2);
    }
    __syncthreads();

    int lane = tid & 31, wrp = tid >> 5;
    float* Sb = g_S + b * (NPOS * NPOS);

    #pragma unroll 1
    for (int r = 0; r < 4; r++) {
        int xl = wrp + 8 * r;
        if (xl >= 28) break;
        int x = x0 + xl;

        ull xc[16];
        #pragma unroll
        for (int c2 = 0; c2 < 16; c2++)
            xc[c2] = *reinterpret_cast<const ull*>(s_yc + c2 * 200 + x);   // broadcast

        #pragma unroll 1
        for (int m = 0; m < 4; m++) {
            int pr = lane + 32 * m;
            if (pr >= 98) break;
            int y0 = 2 * pr;
            ull acc0 = 0ull, acc1 = 0ull;
            #pragma unroll
            for (int c2 = 0; c2 < 16; c2++) {
                ulonglong2 v = *reinterpret_cast<const ulonglong2*>(s_yc + c2 * 200 + y0);
                acc0 = f2fma(xc[c2], v.x, acc0);
                acc1 = f2fma(xc[c2], v.y, acc1);
            }
            float2 rr;
            rr.x = f2sum(acc0);
            rr.y = f2sum(acc1);
            *reinterpret_cast<float2*>(Sb + x * NPOS + y0) = rr;
        }
    }
}

// ---------------- Kernel C1: expand off-diagonal rows (q != p), G computed inline ----------------
__global__ __launch_bounds__(256) void k_expand_off(const float* __restrict__ w_sigma,
                                                    float* __restrict__ out) {
    __shared__ float  s_g[PP];
    __shared__ float4 s_sp[16];

    int tid = threadIdx.x;
    int p = blockIdx.x, b = blockIdx.y;
    int bp = b * PP + p;
    int pr = p / 10, pc = p % 10;

    // inline Gram row: G[p][q] = 25-shift diagonal sum of S
    if (tid < PP) {
        int q  = tid;
        int qr = q / 10, qc = q % 10;
        const float* s = g_S + b * (NPOS * NPOS) + (pr * 14 + pc) * NPOS + (qr * 14 + qc);
        float acc = 0.f;
        #pragma unroll
        for (int i = 0; i < KS; i++)
            #pragma unroll
            for (int j = 0; j < KS; j++)
                acc += __ldg(s + (i * 14 + j) * (NPOS + 1));
        s_g[q] = acc;
    }
    if (tid >= 128 && tid < 144) {
        int k4 = (tid - 128) * 4;
        float4 sp;
        sp.x = log1pf(expf(w_sigma[k4]));
        sp.y = log1pf(expf(w_sigma[k4 + 1]));
        sp.z = log1pf(expf(w_sigma[k4 + 2]));
        sp.w = log1pf(expf(w_sigma[k4 + 3]));
        s_sp[tid - 128] = sp;
    }
    __syncthreads();

    float* orow = out + BB * PP * KK + bp * (PP * KK);

    #pragma unroll
    for (int it = 0; it < 7; it++) {
        int v = tid + it * 256;
        if (v < PP * 16) {
            int q = v >> 4;
            if (q == p) continue;                    // diagonal row handled elsewhere
            int kc = v & 15, k4 = kc * 4;
            float g = s_g[q];
            float4 sp = s_sp[kc];
            float4 r;
            r.x = sp.x * g; r.y = sp.y * g; r.z = sp.z * g; r.w = sp.w * g;
            r.x = isfinite(r.x) ? r.x : 0.f;
            r.y = isfinite(r.y) ? r.y : 0.f;
            r.z = isfinite(r.z) ? r.z : 0.f;
            r.w = isfinite(r.w) ? r.w : 0.f;
            if (q == k4)     r.x = fabsf(r.x);
            if (q == k4 + 1) r.y = fabsf(r.y);
            if (q == k4 + 2) r.z = fabsf(r.z);
            if (q == k4 + 3) r.w = fabsf(r.w);
            *reinterpret_cast<float4*>(orow + 4 * v) = r;
        }
    }
}

// ---------------- Kernel C2: expand diagonal rows (q == p), G[p][p] inline ----------------
__global__ __launch_bounds__(256) void k_expand_diag(const float* __restrict__ w_sigma,
                                                     float* __restrict__ out) {
    int v = blockIdx.x * 256 + threadIdx.x;          // float4 index, 51200 total
    if (v >= BB * PP * 16) return;
    int bp = v >> 4, kc = v & 15, k4 = kc * 4;
    int b = bp / PP, p = bp - b * PP;
    int pr = p / 10, pc = p % 10;

    // G[p][p] = 25-shift diagonal sum of S at diagonal base
    const float* s = g_S + b * (NPOS * NPOS) + (pr * 14 + pc) * (NPOS + 1);
    float g = 0.f;
    #pragma unroll
    for (int i = 0; i < KS; i++)
        #pragma unroll
        for (int j = 0; j < KS; j++)
            g += __ldg(s + (i * 14 + j) * (NPOS + 1));

    float4 dv4 = *reinterpret_cast<const float4*>(g_dv + bp * KK + k4);
    float4 r;
    r.x = log1pf(expf(w_sigma[k4]))     * g + dv4.x;
    r.y = log1pf(expf(w_sigma[k4 + 1])) * g + dv4.y;
    r.z = log1pf(expf(w_sigma[k4 + 2])) * g + dv4.z;
    r.w = log1pf(expf(w_sigma[k4 + 3])) * g + dv4.w;
    r.x = isfinite(r.x) ? r.x : 0.f;
    r.y = isfinite(r.y) ? r.y : 0.f;
    r.z = isfinite(r.z) ? r.z : 0.f;
    r.w = isfinite(r.w) ? r.w : 0.f;
    if (p == k4)     r.x = fabsf(r.x);
    if (p == k4 + 1) r.y = fabsf(r.y);
    if (p == k4 + 2) r.z = fabsf(r.z);
    if (p == k4 + 3) r.w = fabsf(r.w);
    float* orow = out + BB * PP * KK + bp * (PP * KK) + p * KK;
    *reinterpret_cast<float4*>(orow + k4) = r;
}

// ---------------- launch ----------------
extern "C" void kernel_launch(void* const* d_in, const int* in_sizes, int n_in,
                              void* d_out, int out_size) {
    const float* mu_in    = (const float*)d_in[0];
    const float* Sigma_in = (const float*)d_in[1];
    const float* w_mu     = (const float*)d_in[2];
    const float* w_sigma  = (const float*)d_in[3];
    float* out = (float*)d_out;

    static cudaStream_t s2 = nullptr;
    static cudaEvent_t  eFork = nullptr, eJoin = nullptr;
    if (s2 == nullptr) {
        cudaStreamCreateWithFlags(&s2, cudaStreamNonBlocking);
        cudaEventCreateWithFlags(&eFork, cudaEventDisableTiming);
        cudaEventCreateWithFlags(&eJoin, cudaEventDisableTiming);
    }

    // side stream: S, then off-diagonal Sigma expansion (G computed inline)
    cudaEventRecord(eFork, 0);
    cudaStreamWaitEvent(s2, eFork, 0);
    k_gram_s<<<dim3(7, BB), 256, 0, s2>>>(mu_in);
    k_expand_off<<<dim3(PP, BB), 256, 0, s2>>>(w_sigma, out);
    cudaEventRecord(eJoin, s2);

    // main stream: mu path (weights read directly from w_mu)
    k_mu_diag<<<dim3(5, 2, BB), 160>>>(mu_in, Sigma_in, w_mu, w_sigma, out);

    cudaStreamWaitEvent(0, eJoin, 0);
    k_expand_diag<<<200, 256>>>(w_sigma, out);
}